// round 4
// baseline (speedup 1.0000x reference)
#include <cuda_runtime.h>
#include <cuda_bf16.h>
#include <cstdint>

// ============================================================================
// VQ-VAE vector quantizer — sm_100 (compute_100 PTX; NO tcgen05).
// bf16 HMMA GEMM for d_out + candidates; exact fp32 rescore that SIMULATES
// the reference's fp32 rounding grid:
//     d = fl( fl(zn + en) - 2*S ),  zn/en = sequential ascending fp32 sums,
// argmin with strict-< (lower index wins ties) over rounded values.
//
// Outputs (flattened f32 tuple):
//   [0, 8388608)      z_q_out  (NCHW)
//   [8388608]         loss
//   [8388609,8421377) min_idx as float
//   [8421377,...)     d_out [N,1024]
// ============================================================================

#define N_TOK   32768
#define C_DIM   256
#define N_E     1024
#define T_TILES 256
#define C8_T    8
#define KQ_N    4
#define TILE_E  8192
#define TILE_B  16384
#define FINF    3.402823466e+38f

#define OUT_ZQ   0ull
#define OUT_LOSS 8388608ull
#define OUT_IDX  8388609ull
#define OUT_D    8421377ull

// ---------------- device scratch --------------------------------------------
__device__ __nv_bfloat16 g_A[T_TILES * KQ_N * TILE_E];   // 16 MB swizzled z tiles
__device__ __nv_bfloat16 g_B[C8_T * KQ_N * TILE_E];      // 512 KB swizzled e tiles
__device__ float  g_znp[T_TILES * KQ_N * 128];           // z-norm partials (for d_out)
__device__ float  g_enp[C8_T * KQ_N * 128];              // e-norm partials (for d_out)
__device__ float  g_enq[N_E];                            // e-norm, EXACT sequential order
__device__ float2 g_cand[N_TOK * 64];                    // (val, idxf) top2 x 32-code col
__device__ double g_lossp[1024];

// ---------------- helpers ----------------------------------------------------
static __device__ __forceinline__ uint32_t sw128(uint32_t o) {
    return o ^ ((o >> 3) & 0x70u);
}
static __device__ __forceinline__ uint32_t smem_u32(const void* p) {
    uint32_t a;
    asm("{ .reg .u64 t; cvta.to.shared.u64 t, %1; cvt.u32.u64 %0, t; }"
        : "=r"(a) : "l"(p));
    return a;
}
#define MBAR_INIT(m, cnt) \
    asm volatile("mbarrier.init.shared.b64 [%0], %1;" :: "r"(m), "r"((uint32_t)(cnt)) : "memory")
#define MBAR_EXPECT_TX(m, bytes) \
    asm volatile("mbarrier.arrive.expect_tx.shared.b64 _, [%0], %1;" :: "r"(m), "r"((uint32_t)(bytes)) : "memory")
static __device__ __forceinline__ void mbar_wait(uint32_t mbar, uint32_t parity) {
    asm volatile(
        "{\n\t.reg .pred P;\n\t"
        "WL_%=:\n\t"
        "mbarrier.try_wait.parity.acquire.cta.shared::cta.b64 P, [%0], %1, 0x989680;\n\t"
        "@P bra.uni WD_%=;\n\t"
        "bra.uni WL_%=;\n\t"
        "WD_%=:\n\t}"
        :: "r"(mbar), "r"(parity) : "memory");
}
static __device__ __forceinline__ void bulk_g2s(uint32_t dst, const void* src,
                                                uint32_t bytes, uint32_t mbar) {
    asm volatile(
        "cp.async.bulk.shared::cluster.global.mbarrier::complete_tx::bytes [%0], [%1], %2, [%3];"
        :: "r"(dst), "l"(src), "r"(bytes), "r"(mbar) : "memory");
}
#define LDSM_X4(r, addr) \
    asm volatile("ldmatrix.sync.aligned.m8n8.x4.shared.b16 {%0,%1,%2,%3}, [%4];" \
                 : "=r"((r)[0]), "=r"((r)[1]), "=r"((r)[2]), "=r"((r)[3]) : "r"(addr))
#define MMA_BF16(c, a, b0, b1) \
    asm volatile("mma.sync.aligned.m16n8k16.row.col.f32.bf16.bf16.f32 " \
                 "{%0,%1,%2,%3}, {%4,%5,%6,%7}, {%8,%9}, {%0,%1,%2,%3};" \
                 : "+f"((c)[0]), "+f"((c)[1]), "+f"((c)[2]), "+f"((c)[3]) \
                 : "r"((a)[0]), "r"((a)[1]), "r"((a)[2]), "r"((a)[3]), "r"(b0), "r"(b1))

static __device__ __forceinline__ void top2_ins(float v, int i,
                                                float& v1, int& i1,
                                                float& v2, int& i2) {
    bool lt1 = (v < v1) || (v == v1 && i < i1);
    if (lt1) { v2 = v1; i2 = i1; v1 = v; i1 = i; }
    else {
        bool lt2 = (v < v2) || (v == v2 && i < i2);
        if (lt2) { v2 = v; i2 = i; }
    }
}

// ============================================================================
// prep_a: z (NCHW f32) -> bf16 SW128 tiles + per-token norm partials.
// ============================================================================
__global__ void prep_a_kernel(const float* __restrict__ z) {
    int kq = blockIdx.x, t = blockIdx.y;
    int n0 = t * 128, b = n0 >> 10, s0 = n0 & 1023;
    __shared__ __nv_bfloat16 sh[TILE_E];
    __shared__ float s_part[128];
    int tid = threadIdx.x;
    int j = tid & 127;
    float acc = 0.0f;
    for (int i = tid; i < TILE_E; i += 256) {
        int cc = i >> 7;
        int c  = kq * 64 + cc;
        float v = z[(((size_t)(b * C_DIM + c)) << 10) + s0 + j];
        acc += v * v;
        *(__nv_bfloat16*)((char*)sh + sw128((uint32_t)(j * 128 + cc * 2))) =
            __float2bfloat16(v);
    }
    if (tid < 128) s_part[j] = acc;
    __syncthreads();
    if (tid >= 128) s_part[j] += acc;
    __syncthreads();
    if (tid < 128) g_znp[(t * 4 + kq) * 128 + j] = s_part[j];

    const uint4* s1 = (const uint4*)sh;
    uint4* d1 = (uint4*)(g_A + (size_t)(t * 4 + kq) * TILE_E);
    for (int i = tid; i < TILE_B / 16; i += 256) d1[i] = s1[i];
}

// ============================================================================
// prep_b: embedding -> bf16 SW128 tiles + norm partials + EXACT sequential en.
// ============================================================================
__global__ void prep_b_kernel(const float* __restrict__ e) {
    int kq = blockIdx.x, c8 = blockIdx.y;
    int r = threadIdx.x;
    int k = c8 * 128 + r;
    __nv_bfloat16* tb = g_B + (size_t)(c8 * 4 + kq) * TILE_E;
    float acc = 0.0f;
    for (int cc = 0; cc < 64; cc++) {
        float v = e[(size_t)k * C_DIM + kq * 64 + cc];
        acc += v * v;
        *(__nv_bfloat16*)((char*)tb + sw128((uint32_t)(r * 128 + cc * 2))) =
            __float2bfloat16(v);
    }
    g_enp[(c8 * 4 + kq) * 128 + r] = acc;
    if (kq == 0) {
        // exact reference-order en: sequential ascending, separate mul/add
        float a = 0.0f;
        for (int c = 0; c < C_DIM; c++) {
            float v = e[(size_t)k * C_DIM + c];
            a = __fadd_rn(a, __fmul_rn(v, v));
        }
        g_enq[k] = a;
    }
}

// ============================================================================
// gemm: 128x128 tile, K=256. 8 warps (2M x 4N), warp 64x32.
// Epilogue: d_out write + top-2 candidates per 32-code column per row.
// ============================================================================
extern __shared__ char dynsmem[];

__global__ void __launch_bounds__(256) gemm_kernel(float* __restrict__ out) {
    __shared__ float s_zn[128];
    __shared__ float s_en[128];
    __shared__ __align__(8) unsigned long long s_mbar[2];

    int bx = blockIdx.x;
    int tId = bx >> 3, c8 = bx & 7;
    int tid = threadIdx.x, lane = tid & 31, wid = tid >> 5;
    int wm = wid >> 2, wn = wid & 3;

    uint32_t sbase = (smem_u32(dynsmem) + 1023u) & ~1023u;
    uint32_t mb0 = smem_u32(&s_mbar[0]);
    uint32_t mb1 = smem_u32(&s_mbar[1]);
    if (tid == 0) { MBAR_INIT(mb0, 1); MBAR_INIT(mb1, 1); }

    if (tid < 128) {
        float a = 0.0f;
        #pragma unroll
        for (int kq = 0; kq < 4; kq++) a += g_znp[(tId * 4 + kq) * 128 + tid];
        s_zn[tid] = a;
    } else {
        int c = tid - 128;
        float a = 0.0f;
        #pragma unroll
        for (int kq = 0; kq < 4; kq++) a += g_enp[(c8 * 4 + kq) * 128 + c];
        s_en[c] = a;
    }
    __syncthreads();

    const char* gA = (const char*)(g_A + (size_t)tId * KQ_N * TILE_E);
    const char* gB = (const char*)(g_B + (size_t)c8 * KQ_N * TILE_E);
    if (tid == 0) {
        #pragma unroll
        for (int k = 0; k < 2; k++) {
            uint32_t mb = k ? mb1 : mb0;
            MBAR_EXPECT_TX(mb, 2 * TILE_B);
            bulk_g2s(sbase + k * 32768, gA + (size_t)k * TILE_B, TILE_B, mb);
            bulk_g2s(sbase + k * 32768 + TILE_B, gB + (size_t)k * TILE_B, TILE_B, mb);
        }
    }

    float c_[4][4][4];
    #pragma unroll
    for (int i = 0; i < 4; i++)
        #pragma unroll
        for (int j = 0; j < 4; j++)
            #pragma unroll
            for (int k = 0; k < 4; k++) c_[i][j][k] = 0.0f;

    int rA = (lane & 7) + (lane & 8);
    uint32_t kselA = (lane & 16) ? 16u : 0u;
    uint32_t swA = (uint32_t)((rA & 7) << 4);
    uint32_t aoff[4];
    #pragma unroll
    for (int i = 0; i < 4; i++)
        aoff[i] = (uint32_t)((wm * 64 + i * 16 + rA) * 128);
    int nB = (lane & 7) + ((lane & 16) >> 1);
    uint32_t kselB = (lane & 8) ? 16u : 0u;
    uint32_t swB = (uint32_t)((nB & 7) << 4);
    uint32_t boff[2];
    #pragma unroll
    for (int j2 = 0; j2 < 2; j2++)
        boff[j2] = (uint32_t)((wn * 32 + j2 * 16 + nB) * 128) + TILE_B;

    for (int kq = 0; kq < 4; kq++) {
        int s = kq & 1, ph = (kq >> 1) & 1;
        uint32_t mb = s ? mb1 : mb0;
        mbar_wait(mb, (uint32_t)ph);
        uint32_t stg = sbase + s * 32768;
        #pragma unroll
        for (int ks = 0; ks < 4; ks++) {
            uint32_t a[4][4], bb[2][4];
            #pragma unroll
            for (int i = 0; i < 4; i++)
                LDSM_X4(a[i], stg + aoff[i] + (((uint32_t)(ks * 32) + kselA) ^ swA));
            #pragma unroll
            for (int j2 = 0; j2 < 2; j2++)
                LDSM_X4(bb[j2], stg + boff[j2] + (((uint32_t)(ks * 32) + kselB) ^ swB));
            #pragma unroll
            for (int i = 0; i < 4; i++) {
                #pragma unroll
                for (int j = 0; j < 4; j++) {
                    MMA_BF16(c_[i][j], a[i], bb[j >> 1][(j & 1) * 2], bb[j >> 1][(j & 1) * 2 + 1]);
                }
            }
        }
        __syncthreads();
        if (tid == 0 && kq < 2) {
            MBAR_EXPECT_TX(mb, 2 * TILE_B);
            bulk_g2s(stg, gA + (size_t)(kq + 2) * TILE_B, TILE_B, mb);
            bulk_g2s(stg + TILE_B, gB + (size_t)(kq + 2) * TILE_B, TILE_B, mb);
        }
    }

    // ---- epilogue: write d, keep top-2 per 32-code column per row ----
    int g = lane >> 2, q = lane & 3;
    float* dbase = out + OUT_D;
    #pragma unroll
    for (int i = 0; i < 4; i++) {
        #pragma unroll
        for (int h = 0; h < 2; h++) {
            int rl = wm * 64 + i * 16 + h * 8 + g;
            int row_g = tId * 128 + rl;
            float zn = s_zn[rl];
            float* dp = dbase + (size_t)row_g * 1024 + (size_t)(c8 * 128);
            float v1 = FINF, v2 = FINF;
            int i1 = 0x7fffffff, i2 = 0x7fffffff;
            #pragma unroll
            for (int j = 0; j < 4; j++) {
                int cl = wn * 32 + j * 8 + q * 2;
                float d0 = fmaf(-2.0f, c_[i][j][h * 2 + 0], zn + s_en[cl]);
                float d1 = fmaf(-2.0f, c_[i][j][h * 2 + 1], zn + s_en[cl + 1]);
                dp[cl]     = d0;   // OUT_D is odd -> scalar stores only
                dp[cl + 1] = d1;
                top2_ins(d0, cl,     v1, i1, v2, i2);
                top2_ins(d1, cl + 1, v1, i1, v2, i2);
            }
            #pragma unroll
            for (int off = 1; off <= 2; off <<= 1) {
                float ov1 = __shfl_xor_sync(0xffffffffu, v1, off);
                int   oi1 = __shfl_xor_sync(0xffffffffu, i1, off);
                float ov2 = __shfl_xor_sync(0xffffffffu, v2, off);
                int   oi2 = __shfl_xor_sync(0xffffffffu, i2, off);
                top2_ins(ov1, oi1, v1, i1, v2, i2);
                top2_ins(ov2, oi2, v1, i1, v2, i2);
            }
            if (q == 0) {
                size_t cb = (size_t)row_g * 64 + (size_t)(c8 * 8 + wn * 2);
                g_cand[cb]     = make_float2(v1, (float)(c8 * 128 + i1));
                g_cand[cb + 1] = make_float2(v2, (float)(c8 * 128 + i2));
            }
        }
    }
}

// ============================================================================
// rescore: exact fp32 S for 64 candidates/token, simulate reference rounding
//   d = fl(fl(zn_seq + en_seq) - 2*S), argmin strict-< lower-index-ties.
// Then z_q gather + loss. 1024 blocks x 256 threads; block = 32 tokens.
// ============================================================================
__global__ void __launch_bounds__(256) rescore_kernel(const float* __restrict__ z,
                                                      const float* __restrict__ e,
                                                      float* __restrict__ out) {
    int gblk = blockIdx.x;
    int base = gblk * 32, b = base >> 10, s0 = base & 1023;
    __shared__ float s_z[C_DIM * 33];     // [c][token], stride 33
    __shared__ float s_S[32 * 64];
    __shared__ float s_en[N_E];
    __shared__ float s_zn[32];
    __shared__ int   s_win[32];
    __shared__ float s_red[8];
    int tid = threadIdx.x, lane = tid & 31, w = tid >> 5;

    for (int c = w; c < C_DIM; c += 8)
        s_z[c * 33 + lane] = z[(((size_t)(b * C_DIM + c)) << 10) + s0 + lane];
    #pragma unroll
    for (int i = 0; i < N_E / 256; i++) s_en[i * 256 + tid] = g_enq[i * 256 + tid];
    __syncthreads();

    // warp 0: exact sequential zn per token (reference reduction order guess)
    if (w == 0) {
        float a = 0.0f;
        for (int c = 0; c < C_DIM; c++) {
            float v = s_z[c * 33 + lane];
            a = __fadd_rn(a, __fmul_rn(v, v));
        }
        s_zn[lane] = a;
    } else {
        // warps 1..7: candidate dot products (fp32, any order is fine)
        for (int task = (w - 1); task < 32 * 64; task += 7) {
            int tt = task >> 6, cd = task & 63;
            int ci = (int)g_cand[(size_t)(base + tt) * 64 + cd].y;
            const float* er = e + (size_t)ci * C_DIM;
            float p = 0.0f;
            #pragma unroll
            for (int c = lane; c < C_DIM; c += 32)
                p = fmaf(er[c], s_z[c * 33 + tt], p);
            #pragma unroll
            for (int off = 16; off > 0; off >>= 1)
                p += __shfl_xor_sync(0xffffffffu, p, off);
            if (lane == 0) s_S[tt * 64 + cd] = p;
        }
    }
    __syncthreads();

    // winner per token: simulated reference grid + lower-index tie-break
    if (tid < 32) {
        int tt = tid;
        float zn = s_zn[tt];
        float best = FINF;
        int bi = 0x7fffffff;
        for (int cd = 0; cd < 64; cd++) {
            int ci = (int)g_cand[(size_t)(base + tt) * 64 + cd].y;
            float t1 = __fadd_rn(zn, s_en[ci]);
            float d  = __fsub_rn(t1, __fmul_rn(2.0f, s_S[tt * 64 + cd]));
            if (d < best || (d == best && ci < bi)) { best = d; bi = ci; }
        }
        s_win[tt] = bi;
        out[OUT_IDX + base + tt] = (float)bi;
    }
    __syncthreads();

    // gather z_q (straight-through arithmetic) + loss partial
    float acc = 0.0f;
    for (int rep = 0; rep < 4; rep++) {
        int tt = w + rep * 8;
        int chosen = s_win[tt];
        for (int c = lane; c < C_DIM; c += 32) {
            float ev = e[(size_t)chosen * C_DIM + c];
            float zv = s_z[c * 33 + tt];
            float diff = ev - zv;
            s_z[c * 33 + tt] = zv + diff;
            acc += diff * diff;
        }
    }
    #pragma unroll
    for (int off = 16; off > 0; off >>= 1)
        acc += __shfl_xor_sync(0xffffffffu, acc, off);
    if (lane == 0) s_red[w] = acc;
    __syncthreads();
    if (tid == 0) {
        double t = 0.0;
        #pragma unroll
        for (int k = 0; k < 8; k++) t += (double)s_red[k];
        g_lossp[gblk] = t;
    }
    __syncthreads();
    for (int c = w; c < C_DIM; c += 8)
        out[OUT_ZQ + (((size_t)(b * C_DIM + c)) << 10) + s0 + lane] = s_z[c * 33 + lane];
}

// ============================================================================
__global__ void finalize_kernel(float* __restrict__ out) {
    __shared__ double sr[256];
    int tid = threadIdx.x;
    double a = 0.0;
    #pragma unroll
    for (int k = 0; k < 4; k++) a += g_lossp[tid * 4 + k];
    sr[tid] = a;
    __syncthreads();
    for (int st = 128; st > 0; st >>= 1) {
        if (tid < st) sr[tid] += sr[tid + st];
        __syncthreads();
    }
    if (tid == 0) out[OUT_LOSS] = (float)(1.25 * sr[0] / 8388608.0);
}

// ============================================================================
extern "C" void kernel_launch(void* const* d_in, const int* in_sizes, int n_in,
                              void* d_out, int out_size) {
    const float* z   = (const float*)d_in[0];
    const float* emb = (const float*)d_in[1];
    if (n_in >= 2 && in_sizes[0] == N_E * C_DIM) {
        emb = (const float*)d_in[0];
        z   = (const float*)d_in[1];
    }
    float* out = (float*)d_out;

    cudaFuncSetAttribute(gemm_kernel,
                         cudaFuncAttributeMaxDynamicSharedMemorySize, 66560);

    prep_a_kernel<<<dim3(KQ_N, T_TILES), 256>>>(z);
    prep_b_kernel<<<dim3(KQ_N, C8_T), 128>>>(emb);
    gemm_kernel<<<T_TILES * C8_T, 256, 66560>>>(out);
    rescore_kernel<<<N_TOK / 32, 256>>>(z, emb, out);
    finalize_kernel<<<1, 256>>>(out);
}

// round 5
// speedup vs baseline: 2.0435x; 2.0435x over previous
#include <cuda_runtime.h>
#include <cuda_bf16.h>
#include <cstdint>

// ============================================================================
// VQ-VAE vector quantizer — sm_100 (compute_100 PTX; NO tcgen05).
// bf16 HMMA GEMM for d_out + top-2/32-col candidates; margin-filtered exact
// fp32 rescore that SIMULATES the reference's fp32 rounding grid:
//     d = fl( fl(zn + en) - 2*S ),  zn/en = sequential ascending fp32 sums,
// argmin with strict-< (lower index wins ties) over rounded values.
//
// Outputs (flattened f32 tuple):
//   [0, 8388608)      z_q_out  (NCHW)
//   [8388608]         loss
//   [8388609,8421377) min_idx as float
//   [8421377,...)     d_out [N,1024]
// ============================================================================

#define N_TOK   32768
#define C_DIM   256
#define N_E     1024
#define T_TILES 256
#define C8_T    8
#define KQ_N    4
#define TILE_E  8192
#define TILE_B  16384
#define FINF    3.402823466e+38f
#define MARGIN2 8e-4f

#define OUT_ZQ   0ull
#define OUT_LOSS 8388608ull
#define OUT_IDX  8388609ull
#define OUT_D    8421377ull

#define GEMM_SMEM 69632   // >= 2*32768 stage + pad, >= 128*132*4 epilogue stage

// ---------------- device scratch --------------------------------------------
__device__ __nv_bfloat16 g_A[T_TILES * KQ_N * TILE_E];   // 16 MB swizzled z tiles
__device__ __nv_bfloat16 g_B[C8_T * KQ_N * TILE_E];      // 512 KB swizzled e tiles
__device__ float  g_znp[T_TILES * KQ_N * 128];           // z-norm partials (for d_out)
__device__ float  g_enp[C8_T * KQ_N * 128];              // e-norm partials (for d_out)
__device__ float  g_enq[N_E];                            // e-norm, EXACT sequential order
__device__ float2 g_cand[N_TOK * 64];                    // (val, idxf) top2 x 32-code col
__device__ double g_lossp[1024];

// ---------------- helpers ----------------------------------------------------
static __device__ __forceinline__ uint32_t sw128(uint32_t o) {
    return o ^ ((o >> 3) & 0x70u);
}
static __device__ __forceinline__ uint32_t smem_u32(const void* p) {
    uint32_t a;
    asm("{ .reg .u64 t; cvta.to.shared.u64 t, %1; cvt.u32.u64 %0, t; }"
        : "=r"(a) : "l"(p));
    return a;
}
#define MBAR_INIT(m, cnt) \
    asm volatile("mbarrier.init.shared.b64 [%0], %1;" :: "r"(m), "r"((uint32_t)(cnt)) : "memory")
#define MBAR_EXPECT_TX(m, bytes) \
    asm volatile("mbarrier.arrive.expect_tx.shared.b64 _, [%0], %1;" :: "r"(m), "r"((uint32_t)(bytes)) : "memory")
static __device__ __forceinline__ void mbar_wait(uint32_t mbar, uint32_t parity) {
    asm volatile(
        "{\n\t.reg .pred P;\n\t"
        "WL_%=:\n\t"
        "mbarrier.try_wait.parity.acquire.cta.shared::cta.b64 P, [%0], %1, 0x989680;\n\t"
        "@P bra.uni WD_%=;\n\t"
        "bra.uni WL_%=;\n\t"
        "WD_%=:\n\t}"
        :: "r"(mbar), "r"(parity) : "memory");
}
static __device__ __forceinline__ void bulk_g2s(uint32_t dst, const void* src,
                                                uint32_t bytes, uint32_t mbar) {
    asm volatile(
        "cp.async.bulk.shared::cluster.global.mbarrier::complete_tx::bytes [%0], [%1], %2, [%3];"
        :: "r"(dst), "l"(src), "r"(bytes), "r"(mbar) : "memory");
}
#define LDSM_X4(r, addr) \
    asm volatile("ldmatrix.sync.aligned.m8n8.x4.shared.b16 {%0,%1,%2,%3}, [%4];" \
                 : "=r"((r)[0]), "=r"((r)[1]), "=r"((r)[2]), "=r"((r)[3]) : "r"(addr))
#define MMA_BF16(c, a, b0, b1) \
    asm volatile("mma.sync.aligned.m16n8k16.row.col.f32.bf16.bf16.f32 " \
                 "{%0,%1,%2,%3}, {%4,%5,%6,%7}, {%8,%9}, {%0,%1,%2,%3};" \
                 : "+f"((c)[0]), "+f"((c)[1]), "+f"((c)[2]), "+f"((c)[3]) \
                 : "r"((a)[0]), "r"((a)[1]), "r"((a)[2]), "r"((a)[3]), "r"(b0), "r"(b1))

static __device__ __forceinline__ void top2_ins(float v, int i,
                                                float& v1, int& i1,
                                                float& v2, int& i2) {
    bool lt1 = (v < v1) || (v == v1 && i < i1);
    if (lt1) { v2 = v1; i2 = i1; v1 = v; i1 = i; }
    else {
        bool lt2 = (v < v2) || (v == v2 && i < i2);
        if (lt2) { v2 = v; i2 = i; }
    }
}

// ============================================================================
// prep_a: z (NCHW f32) -> bf16 SW128 tiles + per-token norm partials.
// ============================================================================
__global__ void prep_a_kernel(const float* __restrict__ z) {
    int kq = blockIdx.x, t = blockIdx.y;
    int n0 = t * 128, b = n0 >> 10, s0 = n0 & 1023;
    __shared__ __nv_bfloat16 sh[TILE_E];
    __shared__ float s_part[128];
    int tid = threadIdx.x;
    int j = tid & 127;
    float acc = 0.0f;
    for (int i = tid; i < TILE_E; i += 256) {
        int cc = i >> 7;
        int c  = kq * 64 + cc;
        float v = z[(((size_t)(b * C_DIM + c)) << 10) + s0 + j];
        acc += v * v;
        *(__nv_bfloat16*)((char*)sh + sw128((uint32_t)(j * 128 + cc * 2))) =
            __float2bfloat16(v);
    }
    if (tid < 128) s_part[j] = acc;
    __syncthreads();
    if (tid >= 128) s_part[j] += acc;
    __syncthreads();
    if (tid < 128) g_znp[(t * 4 + kq) * 128 + j] = s_part[j];

    const uint4* s1 = (const uint4*)sh;
    uint4* d1 = (uint4*)(g_A + (size_t)(t * 4 + kq) * TILE_E);
    for (int i = tid; i < TILE_B / 16; i += 256) d1[i] = s1[i];
}

// ============================================================================
// prep_b: embedding -> bf16 SW128 tiles + norm partials + EXACT sequential en.
// ============================================================================
__global__ void prep_b_kernel(const float* __restrict__ e) {
    int kq = blockIdx.x, c8 = blockIdx.y;
    int r = threadIdx.x;
    int k = c8 * 128 + r;
    __nv_bfloat16* tb = g_B + (size_t)(c8 * 4 + kq) * TILE_E;
    float acc = 0.0f;
    for (int cc = 0; cc < 64; cc++) {
        float v = e[(size_t)k * C_DIM + kq * 64 + cc];
        acc += v * v;
        *(__nv_bfloat16*)((char*)tb + sw128((uint32_t)(r * 128 + cc * 2))) =
            __float2bfloat16(v);
    }
    g_enp[(c8 * 4 + kq) * 128 + r] = acc;
    if (kq == 0) {
        float a = 0.0f;
        for (int c = 0; c < C_DIM; c++) {
            float v = e[(size_t)k * C_DIM + c];
            a = __fadd_rn(a, __fmul_rn(v, v));
        }
        g_enq[k] = a;
    }
}

// ============================================================================
// gemm: 128x128 tile, K=256. 8 warps (2M x 4N), warp 64x32.
// Epilogue: top-2 per 32-col candidates + smem-staged coalesced d_out write.
// ============================================================================
extern __shared__ char dynsmem[];

__global__ void __launch_bounds__(256) gemm_kernel(float* __restrict__ out) {
    __shared__ float s_zn[128];
    __shared__ float s_en[128];
    __shared__ __align__(8) unsigned long long s_mbar[2];

    int bx = blockIdx.x;
    int tId = bx >> 3, c8 = bx & 7;
    int tid = threadIdx.x, lane = tid & 31, wid = tid >> 5;
    int wm = wid >> 2, wn = wid & 3;

    uint32_t sbase = (smem_u32(dynsmem) + 1023u) & ~1023u;
    uint32_t mb0 = smem_u32(&s_mbar[0]);
    uint32_t mb1 = smem_u32(&s_mbar[1]);
    if (tid == 0) { MBAR_INIT(mb0, 1); MBAR_INIT(mb1, 1); }

    if (tid < 128) {
        float a = 0.0f;
        #pragma unroll
        for (int kq = 0; kq < 4; kq++) a += g_znp[(tId * 4 + kq) * 128 + tid];
        s_zn[tid] = a;
    } else {
        int c = tid - 128;
        float a = 0.0f;
        #pragma unroll
        for (int kq = 0; kq < 4; kq++) a += g_enp[(c8 * 4 + kq) * 128 + c];
        s_en[c] = a;
    }
    __syncthreads();

    const char* gA = (const char*)(g_A + (size_t)tId * KQ_N * TILE_E);
    const char* gB = (const char*)(g_B + (size_t)c8 * KQ_N * TILE_E);
    if (tid == 0) {
        #pragma unroll
        for (int k = 0; k < 2; k++) {
            uint32_t mb = k ? mb1 : mb0;
            MBAR_EXPECT_TX(mb, 2 * TILE_B);
            bulk_g2s(sbase + k * 32768, gA + (size_t)k * TILE_B, TILE_B, mb);
            bulk_g2s(sbase + k * 32768 + TILE_B, gB + (size_t)k * TILE_B, TILE_B, mb);
        }
    }

    float c_[4][4][4];
    #pragma unroll
    for (int i = 0; i < 4; i++)
        #pragma unroll
        for (int j = 0; j < 4; j++)
            #pragma unroll
            for (int k = 0; k < 4; k++) c_[i][j][k] = 0.0f;

    int rA = (lane & 7) + (lane & 8);
    uint32_t kselA = (lane & 16) ? 16u : 0u;
    uint32_t swA = (uint32_t)((rA & 7) << 4);
    uint32_t aoff[4];
    #pragma unroll
    for (int i = 0; i < 4; i++)
        aoff[i] = (uint32_t)((wm * 64 + i * 16 + rA) * 128);
    int nB = (lane & 7) + ((lane & 16) >> 1);
    uint32_t kselB = (lane & 8) ? 16u : 0u;
    uint32_t swB = (uint32_t)((nB & 7) << 4);
    uint32_t boff[2];
    #pragma unroll
    for (int j2 = 0; j2 < 2; j2++)
        boff[j2] = (uint32_t)((wn * 32 + j2 * 16 + nB) * 128) + TILE_B;

    for (int kq = 0; kq < 4; kq++) {
        int s = kq & 1, ph = (kq >> 1) & 1;
        uint32_t mb = s ? mb1 : mb0;
        mbar_wait(mb, (uint32_t)ph);
        uint32_t stg = sbase + s * 32768;
        #pragma unroll
        for (int ks = 0; ks < 4; ks++) {
            uint32_t a[4][4], bb[2][4];
            #pragma unroll
            for (int i = 0; i < 4; i++)
                LDSM_X4(a[i], stg + aoff[i] + (((uint32_t)(ks * 32) + kselA) ^ swA));
            #pragma unroll
            for (int j2 = 0; j2 < 2; j2++)
                LDSM_X4(bb[j2], stg + boff[j2] + (((uint32_t)(ks * 32) + kselB) ^ swB));
            #pragma unroll
            for (int i = 0; i < 4; i++) {
                #pragma unroll
                for (int j = 0; j < 4; j++) {
                    MMA_BF16(c_[i][j], a[i], bb[j >> 1][(j & 1) * 2], bb[j >> 1][(j & 1) * 2 + 1]);
                }
            }
        }
        __syncthreads();
        if (tid == 0 && kq < 2) {
            MBAR_EXPECT_TX(mb, 2 * TILE_B);
            bulk_g2s(stg, gA + (size_t)(kq + 2) * TILE_B, TILE_B, mb);
            bulk_g2s(stg + TILE_B, gB + (size_t)(kq + 2) * TILE_B, TILE_B, mb);
        }
    }

    // ---- epilogue: d -> smem stage (stride 132) + top-2 per 32-col ----
    float* sd = (float*)dynsmem;       // 128 x 132 floats = 67584 B
    int g = lane >> 2, q = lane & 3;
    #pragma unroll
    for (int i = 0; i < 4; i++) {
        #pragma unroll
        for (int h = 0; h < 2; h++) {
            int rl = wm * 64 + i * 16 + h * 8 + g;
            int row_g = tId * 128 + rl;
            float zn = s_zn[rl];
            float v1 = FINF, v2 = FINF;
            int i1 = 0x7fffffff, i2 = 0x7fffffff;
            #pragma unroll
            for (int j = 0; j < 4; j++) {
                int cl = wn * 32 + j * 8 + q * 2;
                float d0 = fmaf(-2.0f, c_[i][j][h * 2 + 0], zn + s_en[cl]);
                float d1 = fmaf(-2.0f, c_[i][j][h * 2 + 1], zn + s_en[cl + 1]);
                *(float2*)&sd[rl * 132 + cl] = make_float2(d0, d1);
                top2_ins(d0, cl,     v1, i1, v2, i2);
                top2_ins(d1, cl + 1, v1, i1, v2, i2);
            }
            #pragma unroll
            for (int off = 1; off <= 2; off <<= 1) {
                float ov1 = __shfl_xor_sync(0xffffffffu, v1, off);
                int   oi1 = __shfl_xor_sync(0xffffffffu, i1, off);
                float ov2 = __shfl_xor_sync(0xffffffffu, v2, off);
                int   oi2 = __shfl_xor_sync(0xffffffffu, i2, off);
                top2_ins(ov1, oi1, v1, i1, v2, i2);
                top2_ins(ov2, oi2, v1, i1, v2, i2);
            }
            if (q == 0) {
                size_t cb = (size_t)row_g * 64 + (size_t)(c8 * 8 + wn * 2);
                g_cand[cb]     = make_float2(v1, (float)(c8 * 128 + i1));
                g_cand[cb + 1] = make_float2(v2, (float)(c8 * 128 + i2));
            }
        }
    }
    __syncthreads();

    // coalesced d_out store: warp per row, 4 chunks of 32 cols
    float* dbase = out + OUT_D + (size_t)(tId * 128) * 1024 + (size_t)(c8 * 128);
    #pragma unroll
    for (int it = 0; it < 16; it++) {
        int r = wid + it * 8;
        const float* sr = sd + r * 132;
        float* dp = dbase + (size_t)r * 1024;
        #pragma unroll
        for (int cchunk = 0; cchunk < 4; cchunk++)
            dp[cchunk * 32 + lane] = sr[cchunk * 32 + lane];
    }
}

// ============================================================================
// rescore v2: margin-filtered exact rescore + gather + loss.
// 1024 blocks x 256 threads; block = 32 tokens; warp = 4 tokens.
// ============================================================================
__global__ void __launch_bounds__(256) rescore_kernel(const float* __restrict__ z,
                                                      const float* __restrict__ e,
                                                      float* __restrict__ out) {
    int gblk = blockIdx.x;
    int base = gblk * 32, b = base >> 10, s0 = base & 1023;
    __shared__ float s_z[C_DIM * 33];     // [c][token], stride 33
    __shared__ float s_zn[32];
    __shared__ int   s_win[32];
    __shared__ float s_red[8];
    int tid = threadIdx.x, lane = tid & 31, w = tid >> 5;

    for (int c = w; c < C_DIM; c += 8)
        s_z[c * 33 + lane] = z[(((size_t)(b * C_DIM + c)) << 10) + s0 + lane];
    __syncthreads();

    // warp 0: exact sequential zn per token (reference reduction order)
    if (w == 0) {
        float a = 0.0f;
        for (int c = 0; c < C_DIM; c++) {
            float v = s_z[c * 33 + lane];
            a = __fadd_rn(a, __fmul_rn(v, v));
        }
        s_zn[lane] = a;
    }
    __syncthreads();

    // each warp resolves 4 tokens
    #pragma unroll
    for (int u = 0; u < 4; u++) {
        int tt = w * 4 + u;
        int token = base + tt;
        float2 cd0 = g_cand[(size_t)token * 64 + lane];
        float2 cd1 = g_cand[(size_t)token * 64 + 32 + lane];
        unsigned long long k0 =
            ((unsigned long long)__float_as_uint(cd0.x) << 32) | (unsigned)(int)cd0.y;
        unsigned long long k1 =
            ((unsigned long long)__float_as_uint(cd1.x) << 32) | (unsigned)(int)cd1.y;
        unsigned long long kb = k0 < k1 ? k0 : k1;
        #pragma unroll
        for (int off = 16; off > 0; off >>= 1) {
            unsigned long long ok = __shfl_xor_sync(0xffffffffu, kb, off);
            if (ok < kb) kb = ok;
        }
        float bestv = __uint_as_float((unsigned)(kb >> 32));
        float thr = bestv + MARGIN2;
        unsigned m0 = __ballot_sync(0xffffffffu, cd0.x <= thr);
        unsigned m1 = __ballot_sync(0xffffffffu, cd1.x <= thr);
        int winner;
        if (__popc(m0) + __popc(m1) == 1) {
            winner = (int)(unsigned)(kb & 0xffffffffu);   // unique: no grid tie possible
        } else {
            // exact path: simulate reference grid for all qualifying candidates
            float zn = s_zn[tt];
            float best = FINF;
            int bi = 0x7fffffff;
            #pragma unroll
            for (int slot = 0; slot < 2; slot++) {
                unsigned mm = slot ? m1 : m0;
                while (mm) {
                    int src = __ffs(mm) - 1;
                    mm &= mm - 1;
                    float fy = __shfl_sync(0xffffffffu, slot ? cd1.y : cd0.y, src);
                    int ci = (int)fy;
                    const float* er = e + (size_t)ci * C_DIM;
                    float p = 0.0f;
                    #pragma unroll
                    for (int k = 0; k < 8; k++)
                        p = fmaf(er[lane + 32 * k], s_z[(lane + 32 * k) * 33 + tt], p);
                    #pragma unroll
                    for (int off = 16; off > 0; off >>= 1)
                        p += __shfl_xor_sync(0xffffffffu, p, off);
                    float t1 = __fadd_rn(zn, g_enq[ci]);
                    float d  = __fsub_rn(t1, __fmul_rn(2.0f, p));
                    if (d < best || (d == best && ci < bi)) { best = d; bi = ci; }
                }
            }
            winner = bi;
        }
        if (lane == 0) {
            s_win[tt] = winner;
            out[OUT_IDX + token] = (float)winner;
        }
    }
    __syncthreads();

    // gather z_q (straight-through arithmetic) + loss partial
    float acc = 0.0f;
    #pragma unroll
    for (int rep = 0; rep < 4; rep++) {
        int tt = w + rep * 8;
        int chosen = s_win[tt];
        #pragma unroll
        for (int k = 0; k < 8; k++) {
            int c = lane + 32 * k;
            float ev = e[(size_t)chosen * C_DIM + c];
            float zv = s_z[c * 33 + tt];
            float diff = ev - zv;
            s_z[c * 33 + tt] = zv + diff;
            acc += diff * diff;
        }
    }
    #pragma unroll
    for (int off = 16; off > 0; off >>= 1)
        acc += __shfl_xor_sync(0xffffffffu, acc, off);
    if (lane == 0) s_red[w] = acc;
    __syncthreads();
    if (tid == 0) {
        double t = 0.0;
        #pragma unroll
        for (int k = 0; k < 8; k++) t += (double)s_red[k];
        g_lossp[gblk] = t;
    }
    __syncthreads();
    for (int c = w; c < C_DIM; c += 8)
        out[OUT_ZQ + (((size_t)(b * C_DIM + c)) << 10) + s0 + lane] = s_z[c * 33 + lane];
}

// ============================================================================
__global__ void finalize_kernel(float* __restrict__ out) {
    __shared__ double sr[256];
    int tid = threadIdx.x;
    double a = 0.0;
    #pragma unroll
    for (int k = 0; k < 4; k++) a += g_lossp[tid * 4 + k];
    sr[tid] = a;
    __syncthreads();
    for (int st = 128; st > 0; st >>= 1) {
        if (tid < st) sr[tid] += sr[tid + st];
        __syncthreads();
    }
    if (tid == 0) out[OUT_LOSS] = (float)(1.25 * sr[0] / 8388608.0);
}

// ============================================================================
extern "C" void kernel_launch(void* const* d_in, const int* in_sizes, int n_in,
                              void* d_out, int out_size) {
    const float* z   = (const float*)d_in[0];
    const float* emb = (const float*)d_in[1];
    if (n_in >= 2 && in_sizes[0] == N_E * C_DIM) {
        emb = (const float*)d_in[0];
        z   = (const float*)d_in[1];
    }
    float* out = (float*)d_out;

    cudaFuncSetAttribute(gemm_kernel,
                         cudaFuncAttributeMaxDynamicSharedMemorySize, GEMM_SMEM);

    prep_a_kernel<<<dim3(KQ_N, T_TILES), 256>>>(z);
    prep_b_kernel<<<dim3(KQ_N, C8_T), 128>>>(emb);
    gemm_kernel<<<T_TILES * C8_T, 256, GEMM_SMEM>>>(out);
    rescore_kernel<<<N_TOK / 32, 256>>>(z, emb, out);
    finalize_kernel<<<1, 256>>>(out);
}